// round 11
// baseline (speedup 1.0000x reference)
#include <cuda_runtime.h>
#include <cuda_bf16.h>
#include <math.h>

// Problem constants
#define BB 64
#define SS 64
#define HH 512
#define VV 512
#define DEPTH_ 9
#define G3H 1536
#define G6H 3072

typedef __nv_bfloat16 bf16;

// ---------------- scratch (static device arrays) ---------------------------
__device__ float g_h32[2][BB * 512 * HH];
__device__ bf16  g_hhi[2][BB * 512 * HH];
__device__ bf16  g_hlo[2][BB * 512 * HH];
__device__ bf16  g_hidhi[(size_t)BB * 512 * 2 * HH];
__device__ bf16  g_hidlo[(size_t)BB * 512 * 2 * HH];
__device__ bf16  g_wthi[BB * 256 * HH];
__device__ bf16  g_wtlo[BB * 256 * HH];
__device__ bf16  g_ahi[BB * 256 * SS];
__device__ bf16  g_alo[BB * 256 * SS];
__device__ float g_gi[(size_t)BB * 256 * G6H];
__device__ float g_gh[(size_t)BB * 256 * G6H];
__device__ float g_annp[BB * G6H];
__device__ bf16  g_annhi[BB * HH];
__device__ bf16  g_annlo[BB * HH];
__device__ bf16  g_enchi[BB * SS * HH];
__device__ bf16  g_enclo[BB * SS * HH];
__device__ bf16  g_ewhi[(size_t)BB * G6H * SS];
__device__ bf16  g_ewlo[(size_t)BB * G6H * SS];
__device__ bf16  g_wihx_hi[G6H * HH], g_wihx_lo[G6H * HH];
__device__ bf16  g_wiha_hi[G6H * HH], g_wiha_lo[G6H * HH];
__device__ bf16  g_whh_hi[G6H * HH],  g_whh_lo[G6H * HH];
__device__ bf16  g_w1_hi[2 * HH * HH], g_w1_lo[2 * HH * HH];
__device__ bf16  g_w2_hi[VV * 2 * HH], g_w2_lo[VV * 2 * HH];

// epilogue modes
#define MODE_BIAS   0
#define MODE_SIG    1
#define MODE_OUT    2
#define MODE_BIAS2D 3
#define MODE_RAW    4

__device__ __forceinline__ int preorder_index(int d, int pos) {
    int idx = d;
#pragma unroll
    for (int i = 1; i <= DEPTH_; i++) {
        if (i <= d) {
            int bit = (pos >> (d - i)) & 1;
            idx += bit * ((1 << (DEPTH_ - i + 1)) - 1);
        }
    }
    return idx;
}

__device__ __forceinline__ void mma_bf16(float c[4],
                                         unsigned a0, unsigned a1,
                                         unsigned a2, unsigned a3,
                                         unsigned b0, unsigned b1) {
    asm volatile(
        "mma.sync.aligned.m16n8k16.row.col.f32.bf16.bf16.f32 "
        "{%0,%1,%2,%3}, {%4,%5,%6,%7}, {%8,%9}, {%0,%1,%2,%3};"
        : "+f"(c[0]), "+f"(c[1]), "+f"(c[2]), "+f"(c[3])
        : "r"(a0), "r"(a1), "r"(a2), "r"(a3), "r"(b0), "r"(b1));
}

__device__ __forceinline__ void split_bf16(float x, bf16& hi, bf16& lo) {
    hi = __float2bfloat16_rn(x);
    lo = __float2bfloat16_rn(x - __bfloat162float(hi));
}

__device__ __forceinline__ void cp16(void* dst, const void* src) {
    unsigned d = (unsigned)__cvta_generic_to_shared(dst);
    asm volatile("cp.async.cg.shared.global [%0], [%1], 16;"
                 :: "r"(d), "l"(src));
}

// ---------------- split helpers --------------------------------------------
__global__ __launch_bounds__(256) void split_mat(
    const float* __restrict__ src, int rows, int cols, int ld, int coloff,
    bf16* __restrict__ dhi, bf16* __restrict__ dlo)
{
    int idx = blockIdx.x * blockDim.x + threadIdx.x;
    if (idx >= rows * cols) return;
    int r = idx / cols;
    int c = idx - r * cols;
    float v = src[(size_t)r * ld + coloff + c];
    bf16 hi, lo;
    split_bf16(v, hi, lo);
    dhi[idx] = hi;
    dlo[idx] = lo;
}

// enc (S,B,H) -> planes (B,S,H)
__global__ __launch_bounds__(256) void split_enc(
    const float* __restrict__ enc, bf16* __restrict__ dhi,
    bf16* __restrict__ dlo)
{
    int idx = blockIdx.x * blockDim.x + threadIdx.x;
    if (idx >= SS * BB * HH) return;
    int h = idx & (HH - 1);
    int rem = idx >> 9;
    int b = rem & (BB - 1);
    int s = rem >> 6;
    float v = enc[idx];
    bf16 hi, lo;
    split_bf16(v, hi, lo);
    size_t o = ((size_t)b * SS + s) * HH + h;
    dhi[o] = hi;
    dlo[o] = lo;
}

// E (BB*SS rows, G6H cols, fp32) -> ew planes (b, G6H, SS) bf16
__global__ __launch_bounds__(256) void transpose_split(
    const float* __restrict__ E, bf16* __restrict__ dhi,
    bf16* __restrict__ dlo)
{
    __shared__ float tile[64][65];
    int b = blockIdx.x;
    int jt = blockIdx.y;
    int tx = threadIdx.x & 63;
    int ty = threadIdx.x >> 6;
    for (int s = ty; s < 64; s += 4)
        tile[s][tx] = E[((size_t)b * SS + s) * G6H + jt * 64 + tx];
    __syncthreads();
    for (int jr = ty; jr < 64; jr += 4) {
        float v = tile[tx][jr];
        bf16 hi, lo;
        split_bf16(v, hi, lo);
        size_t o = ((size_t)b * G6H + jt * 64 + jr) * SS + tx;
        dhi[o] = hi;
        dlo[o] = lo;
    }
}

// ---------------- hybrid GEMM: HMMA col-tiles + FFMA col-tiles --------------
// C(MxN) = A(MxK) @ Bw(NxK)^T ; A/B pre-split bf16 hi/lo planes (ld = K).
// Columns [0, nx_h*128) computed by the bf16x3 HMMA pipeline (tensor pipe);
// columns [nx_h*128, N) computed by SIMT fp32 FFMA tiles (fma pipe) on
// reconstructed hi+lo operands (same precision class, 1x MACs). The two
// block populations run concurrently in one launch, using both pipes.
#define BM 128
#define BN 128
#define BKT 16
#define PITCH 24
#define NSTAGE 3
#define PLANE_ELE (BM * PITCH)
#define STAGE_ELE (4 * PLANE_ELE)
#define GEMM_SMEM (NSTAGE * STAGE_ELE * 2)

__global__ __launch_bounds__(256, 2) void mma_gemm(
    const bf16* __restrict__ Ahi, const bf16* __restrict__ Alo,
    const bf16* __restrict__ Bhi, const bf16* __restrict__ Blo,
    const float* __restrict__ bias, float* __restrict__ C,
    bf16* __restrict__ Chi, bf16* __restrict__ Clo,
    int M, int N, int K, int mode, int n_nodes, int depth,
    int bsel_n, long long bsel_blk, int nx_h)
{
    extern __shared__ bf16 smem[];

    const int tid = threadIdx.x;
    const int row0 = blockIdx.y * BM;

    const bf16* Bhi_p = Bhi;
    const bf16* Blo_p = Blo;
    if (bsel_n > 0) {
        size_t o = (size_t)(row0 / bsel_n) * bsel_blk;
        Bhi_p += o;
        Blo_p += o;
    }

    if ((int)blockIdx.x >= nx_h) {
        // ================= FFMA path: 128x64 tile on the fma pipe =========
        float* As = (float*)smem;                  // [BKT][132]
        float* Bs = (float*)smem + BKT * 132;      // [BKT][68]
        const int fx = blockIdx.x - nx_h;
        const int col0 = nx_h * 128 + fx * 64;
        const int tx = tid & 15;        // 4 cols each
        const int ty = tid >> 4;        // 8 rows each
        const int la_r = tid >> 1, la_k = (tid & 1) * 8;
        const int lb_r = tid >> 2, lb_k = (tid & 3) * 4;

        int arow = row0 + la_r; if (arow >= M) arow = M - 1;
        const bf16* pAh = Ahi + (size_t)arow * K + la_k;
        const bf16* pAl = Alo + (size_t)arow * K + la_k;
        const bf16* pBh = Bhi_p + (size_t)(col0 + lb_r) * K + lb_k;
        const bf16* pBl = Blo_p + (size_t)(col0 + lb_r) * K + lb_k;

        float acc[8][4];
#pragma unroll
        for (int i = 0; i < 8; i++)
#pragma unroll
            for (int j = 0; j < 4; j++) acc[i][j] = 0.f;

        for (int kt = 0; kt < K; kt += BKT) {
            {
                uint4 h4 = *(const uint4*)(pAh + kt);
                uint4 l4 = *(const uint4*)(pAl + kt);
                const bf16* hv = (const bf16*)&h4;
                const bf16* lv = (const bf16*)&l4;
#pragma unroll
                for (int j = 0; j < 8; j++)
                    As[(la_k + j) * 132 + la_r] =
                        __bfloat162float(hv[j]) + __bfloat162float(lv[j]);
                uint2 bh2 = *(const uint2*)(pBh + kt);
                uint2 bl2 = *(const uint2*)(pBl + kt);
                const bf16* bhv = (const bf16*)&bh2;
                const bf16* blv = (const bf16*)&bl2;
#pragma unroll
                for (int j = 0; j < 4; j++)
                    Bs[(lb_k + j) * 68 + lb_r] =
                        __bfloat162float(bhv[j]) + __bfloat162float(blv[j]);
            }
            __syncthreads();
#pragma unroll
            for (int k = 0; k < BKT; k++) {
                float4 a0 = *(float4*)&As[k * 132 + ty * 8];
                float4 a1 = *(float4*)&As[k * 132 + ty * 8 + 4];
                float4 b  = *(float4*)&Bs[k * 68 + tx * 4];
                float av[8] = {a0.x, a0.y, a0.z, a0.w, a1.x, a1.y, a1.z, a1.w};
                float bv[4] = {b.x, b.y, b.z, b.w};
#pragma unroll
                for (int i = 0; i < 8; i++)
#pragma unroll
                    for (int j = 0; j < 4; j++)
                        acc[i][j] = fmaf(av[i], bv[j], acc[i][j]);
            }
            __syncthreads();
        }

#pragma unroll
        for (int i = 0; i < 8; i++) {
            int r = row0 + ty * 8 + i;
            if (r >= M) continue;
#pragma unroll
            for (int j = 0; j < 4; j++) {
                int c = col0 + tx * 4 + j;
                float v = acc[i][j];
                if (mode == MODE_BIAS) {
                    C[(size_t)r * N + c] = v + bias[c];
                } else if (mode == MODE_SIG) {
                    float sgm = 1.f / (1.f + expf(-(v + bias[c])));
                    bf16 hi, lo;
                    split_bf16(sgm, hi, lo);
                    Chi[(size_t)r * N + c] = hi;
                    Clo[(size_t)r * N + c] = lo;
                } else if (mode == MODE_OUT) {
                    int b = r / n_nodes;
                    int node = r - b * n_nodes;
                    int p = preorder_index(depth, node);
                    C[((size_t)p * BB + b) * VV + c] = v + bias[c];
                } else if (mode == MODE_BIAS2D) {
                    int b = r / n_nodes;
                    C[(size_t)r * N + c] = v + bias[(size_t)b * N + c];
                } else { // MODE_RAW
                    C[(size_t)r * N + c] = v;
                }
            }
        }
        return;
    }

    // ================= HMMA path (unchanged r10 pipeline) =================
    const int lane = tid & 31;
    const int wid = tid >> 5;
    const int warp_m = (wid & 1) * 64;
    const int warp_n = (wid >> 1) * 32;
    const int g = lane >> 2;
    const int t = lane & 3;
    const int col0 = blockIdx.x * BN;

    const int lrow = tid >> 1;
    const int lk = (tid & 1) * 8;

    int arow = row0 + lrow; if (arow >= M) arow = M - 1;
    const size_t aoff = (size_t)arow * K + lk;
    const size_t boff = (size_t)(col0 + lrow) * K + lk;

    const int srow = lrow * PITCH + lk;

    auto load_stage = [&](int kt, int s) {
        bf16* st = smem + s * STAGE_ELE;
        size_t ka = aoff + (size_t)kt * BKT;
        size_t kb = boff + (size_t)kt * BKT;
        cp16(st + srow,                 Ahi + ka);
        cp16(st + PLANE_ELE + srow,     Alo + ka);
        cp16(st + 2 * PLANE_ELE + srow, Bhi_p + kb);
        cp16(st + 3 * PLANE_ELE + srow, Blo_p + kb);
        asm volatile("cp.async.commit_group;" ::: "memory");
    };

    float acc[4][4][4];
#pragma unroll
    for (int mi = 0; mi < 4; mi++)
#pragma unroll
        for (int ni = 0; ni < 4; ni++)
#pragma unroll
            for (int i = 0; i < 4; i++) acc[mi][ni][i] = 0.f;

    const int nkt = K / BKT;

    load_stage(0, 0);
    load_stage(1, 1);

    const int a_r = lane & 15;
    const int a_c = (lane >> 4) * 8;
    const int b_r = lane & 7;
    const int b_c = ((lane >> 3) & 1) * 8;

    int s = 0;
    for (int kt = 0; kt < nkt; kt++) {
        asm volatile("cp.async.wait_group 1;" ::: "memory");
        __syncthreads();

        bf16* st = smem + s * STAGE_ELE;
        bf16* pAhi = st;
        bf16* pAlo = st + PLANE_ELE;
        bf16* pBhi = st + 2 * PLANE_ELE;
        bf16* pBlo = st + 3 * PLANE_ELE;

        unsigned ah[4][4], al[4][4], bh[4][2], bl[4][2];
#pragma unroll
        for (int mi = 0; mi < 4; mi++) {
            int r = warp_m + mi * 16 + a_r;
            unsigned ad = (unsigned)__cvta_generic_to_shared(
                pAhi + r * PITCH + a_c);
            asm volatile("ldmatrix.sync.aligned.m8n8.x4.shared.b16 "
                         "{%0,%1,%2,%3}, [%4];"
                         : "=r"(ah[mi][0]), "=r"(ah[mi][1]),
                           "=r"(ah[mi][2]), "=r"(ah[mi][3]) : "r"(ad));
            unsigned ad2 = (unsigned)__cvta_generic_to_shared(
                pAlo + r * PITCH + a_c);
            asm volatile("ldmatrix.sync.aligned.m8n8.x4.shared.b16 "
                         "{%0,%1,%2,%3}, [%4];"
                         : "=r"(al[mi][0]), "=r"(al[mi][1]),
                           "=r"(al[mi][2]), "=r"(al[mi][3]) : "r"(ad2));
        }
#pragma unroll
        for (int ni = 0; ni < 4; ni++) {
            int r = warp_n + ni * 8 + b_r;
            unsigned bd = (unsigned)__cvta_generic_to_shared(
                pBhi + r * PITCH + b_c);
            asm volatile("ldmatrix.sync.aligned.m8n8.x2.shared.b16 "
                         "{%0,%1}, [%2];"
                         : "=r"(bh[ni][0]), "=r"(bh[ni][1]) : "r"(bd));
            unsigned bd2 = (unsigned)__cvta_generic_to_shared(
                pBlo + r * PITCH + b_c);
            asm volatile("ldmatrix.sync.aligned.m8n8.x2.shared.b16 "
                         "{%0,%1}, [%2];"
                         : "=r"(bl[ni][0]), "=r"(bl[ni][1]) : "r"(bd2));
        }

#pragma unroll
        for (int mi = 0; mi < 4; mi++)
#pragma unroll
            for (int ni = 0; ni < 4; ni++)
                mma_bf16(acc[mi][ni], ah[mi][0], ah[mi][1], ah[mi][2],
                         ah[mi][3], bh[ni][0], bh[ni][1]);
#pragma unroll
        for (int mi = 0; mi < 4; mi++)
#pragma unroll
            for (int ni = 0; ni < 4; ni++)
                mma_bf16(acc[mi][ni], al[mi][0], al[mi][1], al[mi][2],
                         al[mi][3], bh[ni][0], bh[ni][1]);
#pragma unroll
        for (int mi = 0; mi < 4; mi++)
#pragma unroll
            for (int ni = 0; ni < 4; ni++)
                mma_bf16(acc[mi][ni], ah[mi][0], ah[mi][1], ah[mi][2],
                         ah[mi][3], bl[ni][0], bl[ni][1]);

        if (kt + 2 < nkt) {
            int ns = s + 2; if (ns >= NSTAGE) ns -= NSTAGE;
            load_stage(kt + 2, ns);
        } else {
            asm volatile("cp.async.commit_group;" ::: "memory");
        }
        s++; if (s == NSTAGE) s = 0;
    }

    // epilogue
#pragma unroll
    for (int mi = 0; mi < 4; mi++) {
#pragma unroll
        for (int i = 0; i < 4; i++) {
            int r = row0 + warp_m + mi * 16 + g + (i >> 1) * 8;
            if (r >= M) continue;
#pragma unroll
            for (int ni = 0; ni < 4; ni++) {
                int c = col0 + warp_n + ni * 8 + t * 2 + (i & 1);
                float v = acc[mi][ni][i];
                if (mode == MODE_BIAS) {
                    C[(size_t)r * N + c] = v + bias[c];
                } else if (mode == MODE_SIG) {
                    float sgm = 1.f / (1.f + expf(-(v + bias[c])));
                    bf16 hi, lo;
                    split_bf16(sgm, hi, lo);
                    Chi[(size_t)r * N + c] = hi;
                    Clo[(size_t)r * N + c] = lo;
                } else if (mode == MODE_OUT) {
                    int b = r / n_nodes;
                    int node = r - b * n_nodes;
                    int p = preorder_index(depth, node);
                    C[((size_t)p * BB + b) * VV + c] = v + bias[c];
                } else if (mode == MODE_BIAS2D) {
                    int b = r / n_nodes;
                    C[(size_t)r * N + c] = v + bias[(size_t)b * N + c];
                } else { // MODE_RAW
                    C[(size_t)r * N + c] = v;
                }
            }
        }
    }
}

// ---------------- fused attention ------------------------------------------
__global__ __launch_bounds__(128) void attn_kernel(
    const float* __restrict__ h, const float* __restrict__ enc,
    bf16* __restrict__ wthi, bf16* __restrict__ wtlo,
    bf16* __restrict__ ahi, bf16* __restrict__ alo,
    int n, int write_a)
{
    int m = blockIdx.x;
    int b = m / n;
    int t = threadIdx.x;

    __shared__ float sh[HH];
    __shared__ float part[128];
    __shared__ float sc[SS];

    const float* hrow = h + (size_t)m * HH;
    for (int i = t; i < HH; i += 128) sh[i] = hrow[i];
    __syncthreads();

    int s = t & 63;
    int half = t >> 6;
    const float* er = enc + ((size_t)s * BB + b) * HH + half * 256;
    float acc = 0.f;
#pragma unroll 8
    for (int k = 0; k < 256; k++) acc = fmaf(sh[half * 256 + k], er[k], acc);
    part[t] = acc;
    __syncthreads();

    if (t < SS) sc[t] = part[t] + part[t + 64];
    __syncthreads();

    float mx = -1e30f;
#pragma unroll
    for (int i = 0; i < SS; i++) mx = fmaxf(mx, sc[i]);
    __syncthreads();
    if (t < SS) sc[t] = expf(sc[t] - mx);
    __syncthreads();
    float sum = 0.f;
#pragma unroll
    for (int i = 0; i < SS; i++) sum += sc[i];
    float inv = 1.f / sum;

    if (write_a) {
        if (t < SS) {
            float av = sc[t] * inv;
            bf16 hh_, ll_;
            split_bf16(av, hh_, ll_);
            ahi[(size_t)m * SS + t] = hh_;
            alo[(size_t)m * SS + t] = ll_;
        }
        return;
    }

    for (int hi_ = t; hi_ < HH; hi_ += 128) {
        float acc2 = 0.f;
#pragma unroll 8
        for (int s2 = 0; s2 < SS; s2++)
            acc2 = fmaf(sc[s2], enc[((size_t)s2 * BB + b) * HH + hi_], acc2);
        float v = acc2 * inv;
        bf16 h_, l_;
        split_bf16(v, h_, l_);
        wthi[(size_t)m * HH + hi_] = h_;
        wtlo[(size_t)m * HH + hi_] = l_;
    }
}

// ---------------- GRU gate combine (both children fused) -------------------
__global__ __launch_bounds__(256) void gru_combine(
    const float* __restrict__ gi, const float* __restrict__ gh,
    const float* __restrict__ h, float* __restrict__ h32n,
    bf16* __restrict__ hhin, bf16* __restrict__ hlon,
    int n, int total)
{
    int idx = blockIdx.x * blockDim.x + threadIdx.x;
    if (idx >= total) return;
    int k = idx & (HH - 1);
    int child = (idx >> 9) & 1;
    int m = idx >> 10;
    int b = m / n;
    int node = m - b * n;

    size_t gb = (size_t)m * G6H + (size_t)child * G3H;
    float ir = gi[gb + k], iz = gi[gb + HH + k], in_ = gi[gb + 2 * HH + k];
    float hr = gh[gb + k], hz = gh[gb + HH + k], hn = gh[gb + 2 * HH + k];

    float r = 1.f / (1.f + expf(-(ir + hr)));
    float z = 1.f / (1.f + expf(-(iz + hz)));
    float nn = tanhf(in_ + r * hn);
    float hv = h[(size_t)m * HH + k];
    float out = (1.f - z) * nn + z * hv;

    size_t oidx = ((size_t)b * (2 * n) + 2 * node + child) * HH + k;
    h32n[oidx] = out;
    bf16 oh, ol;
    split_bf16(out, oh, ol);
    hhin[oidx] = oh;
    hlon[oidx] = ol;
}

// ---------------- orchestration --------------------------------------------
static void launch_gemm(const bf16* Ah, const bf16* Al,
                        const bf16* Bh, const bf16* Bl,
                        const float* bias, float* C, bf16* Ch, bf16* Cl,
                        int M, int N, int K, int mode, int nn, int dd,
                        int bsn, long long bsb)
{
    // FFMA column fraction ~0.44 (balance: f/19 = (1-f)*3/72)
    int nxf = (N * 44 / 100) / 64;
    nxf &= ~1;                       // keep HMMA width a multiple of 128
    int nx_h = (N - 64 * nxf) / 128;
    dim3 grid(nx_h + nxf, (M + BM - 1) / BM);
    mma_gemm<<<grid, 256, GEMM_SMEM>>>(Ah, Al, Bh, Bl, bias, C, Ch, Cl,
                                       M, N, K, mode, nn, dd, bsn, bsb, nx_h);
}

extern "C" void kernel_launch(void* const* d_in, const int* in_sizes, int n_in,
                              void* d_out, int out_size)
{
    (void)in_sizes; (void)n_in; (void)out_size;
    const float* root  = (const float*)d_in[0];
    const float* ann   = (const float*)d_in[1];
    const float* enc   = (const float*)d_in[2];
    // d_in[3] = source_mask: constant all-True, unused
    const float* w_ih  = (const float*)d_in[4];
    const float* w_hh  = (const float*)d_in[5];
    const float* b_ih  = (const float*)d_in[6];
    const float* b_hh  = (const float*)d_in[7];
    const float* W1    = (const float*)d_in[8];
    const float* b1    = (const float*)d_in[9];
    const float* W2    = (const float*)d_in[10];
    const float* b2    = (const float*)d_in[11];
    float* out = (float*)d_out;

    cudaFuncSetAttribute(mma_gemm,
                         cudaFuncAttributeMaxDynamicSharedMemorySize,
                         GEMM_SMEM);

    float *h32, *gi, *gh, *annp;
    bf16 *hhi, *hlo, *hidhi, *hidlo, *wthi, *wtlo, *ahi, *alo;
    bf16 *annhi, *annlo, *enchi, *enclo, *ewhi, *ewlo;
    bf16 *wihxh, *wihxl, *wihah, *wihal, *whhh, *whhl, *w1h, *w1l, *w2h, *w2l;
    cudaGetSymbolAddress((void**)&h32,   g_h32);
    cudaGetSymbolAddress((void**)&hhi,   g_hhi);
    cudaGetSymbolAddress((void**)&hlo,   g_hlo);
    cudaGetSymbolAddress((void**)&hidhi, g_hidhi);
    cudaGetSymbolAddress((void**)&hidlo, g_hidlo);
    cudaGetSymbolAddress((void**)&wthi,  g_wthi);
    cudaGetSymbolAddress((void**)&wtlo,  g_wtlo);
    cudaGetSymbolAddress((void**)&ahi,   g_ahi);
    cudaGetSymbolAddress((void**)&alo,   g_alo);
    cudaGetSymbolAddress((void**)&gi,    g_gi);
    cudaGetSymbolAddress((void**)&gh,    g_gh);
    cudaGetSymbolAddress((void**)&annp,  g_annp);
    cudaGetSymbolAddress((void**)&annhi, g_annhi);
    cudaGetSymbolAddress((void**)&annlo, g_annlo);
    cudaGetSymbolAddress((void**)&enchi, g_enchi);
    cudaGetSymbolAddress((void**)&enclo, g_enclo);
    cudaGetSymbolAddress((void**)&ewhi,  g_ewhi);
    cudaGetSymbolAddress((void**)&ewlo,  g_ewlo);
    cudaGetSymbolAddress((void**)&wihxh, g_wihx_hi);
    cudaGetSymbolAddress((void**)&wihxl, g_wihx_lo);
    cudaGetSymbolAddress((void**)&wihah, g_wiha_hi);
    cudaGetSymbolAddress((void**)&wihal, g_wiha_lo);
    cudaGetSymbolAddress((void**)&whhh,  g_whh_hi);
    cudaGetSymbolAddress((void**)&whhl,  g_whh_lo);
    cudaGetSymbolAddress((void**)&w1h,   g_w1_hi);
    cudaGetSymbolAddress((void**)&w1l,   g_w1_lo);
    cudaGetSymbolAddress((void**)&w2h,   g_w2_hi);
    cudaGetSymbolAddress((void**)&w2l,   g_w2_lo);

    const size_t HSLOT = (size_t)BB * 512 * HH;
    float* h32buf[2] = {h32, h32 + HSLOT};
    bf16*  hhibuf[2] = {hhi, hhi + HSLOT};
    bf16*  hlobuf[2] = {hlo, hlo + HSLOT};

    cudaMemcpyAsync(h32buf[0], root, (size_t)BB * HH * sizeof(float),
                    cudaMemcpyDeviceToDevice);
    split_mat<<<(BB * HH + 255) / 256, 256>>>(ann, BB, HH, HH, 0,
                                              annhi, annlo);
    split_mat<<<(G6H * HH + 255) / 256, 256>>>(w_ih, G6H, HH, 2 * HH, 0,
                                               wihah, wihal);
    split_mat<<<(BB * HH + 255) / 256, 256>>>(root, BB, HH, HH, 0,
                                              hhibuf[0], hlobuf[0]);
    split_mat<<<(G6H * HH + 255) / 256, 256>>>(w_ih, G6H, HH, 2 * HH, HH,
                                               wihxh, wihxl);

    // annp = ann @ w_ih[:, :, :H]^T + b_ih   (64 x 3072)
    launch_gemm(annhi, annlo, wihah, wihal, b_ih, annp, nullptr, nullptr,
                BB, G6H, HH, MODE_BIAS, 0, 0, 0, 0);

    // E = enc_flat(4096 x 512) @ Wx^T -> (4096 x 3072) fp32 (staged in g_gh)
    split_enc<<<(SS * BB * HH + 255) / 256, 256>>>(enc, enchi, enclo);
    launch_gemm(enchi, enclo, wihxh, wihxl, nullptr, gh, nullptr, nullptr,
                BB * SS, G6H, HH, MODE_RAW, 0, 0, 0, 0);
    transpose_split<<<dim3(BB, G6H / 64), 256>>>(gh, ewhi, ewlo);

    split_mat<<<(G6H * HH + 255) / 256, 256>>>(w_hh, G6H, HH, HH, 0,
                                               whhh, whhl);
    split_mat<<<(2 * HH * HH + 255) / 256, 256>>>(W1, 2 * HH, HH, HH, 0,
                                                  w1h, w1l);
    split_mat<<<(VV * 2 * HH + 255) / 256, 256>>>(W2, VV, 2 * HH, 2 * HH, 0,
                                                  w2h, w2l);

    int cur = 0;
    for (int d = 0; d <= DEPTH_; d++) {
        int n = 1 << d;
        int M = BB * n;

        // hid = sigmoid(h @ W1^T + b1) -> split planes   (M x 1024)
        launch_gemm(hhibuf[cur], hlobuf[cur], w1h, w1l, b1, nullptr,
                    hidhi, hidlo, M, 2 * HH, HH, MODE_SIG, 0, 0, 0, 0);

        // prods -> scattered into out (preorder)   (M x 512)
        launch_gemm(hidhi, hidlo, w2h, w2l, b2, out, nullptr, nullptr,
                    M, VV, 2 * HH, MODE_OUT, n, d, 0, 0);

        if (d < DEPTH_) {
            int use_a = (n >= 128) ? 1 : 0;
            attn_kernel<<<M, 128>>>(h32buf[cur], enc, wthi, wtlo,
                                    ahi, alo, n, use_a);

            if (use_a) {
                // gi = a @ ew[b]^T + annp   (M x 3072, K = 64)
                launch_gemm(ahi, alo, ewhi, ewlo, annp, gi, nullptr, nullptr,
                            M, G6H, SS, MODE_BIAS2D, n, 0,
                            n, (long long)G6H * SS);
            } else {
                // gi = wt @ w_ih[:, :, H:]^T + annp   (M x 3072, K = 512)
                launch_gemm(wthi, wtlo, wihxh, wihxl, annp, gi,
                            nullptr, nullptr,
                            M, G6H, HH, MODE_BIAS2D, n, 0, 0, 0);
            }

            // gh = h @ w_hh^T + b_hh              (M x 3072)
            launch_gemm(hhibuf[cur], hlobuf[cur], whhh, whhl, b_hh, gh,
                        nullptr, nullptr, M, G6H, HH, MODE_BIAS, 0, 0, 0, 0);

            int total = M * 2 * HH;
            gru_combine<<<(total + 255) / 256, 256>>>(
                gi, gh, h32buf[cur], h32buf[cur ^ 1],
                hhibuf[cur ^ 1], hlobuf[cur ^ 1], n, total);

            cur ^= 1;
        }
    }
}

// round 12
// speedup vs baseline: 1.3570x; 1.3570x over previous
#include <cuda_runtime.h>
#include <cuda_bf16.h>
#include <math.h>

// Problem constants
#define BB 64
#define SS 64
#define HH 512
#define VV 512
#define DEPTH_ 9
#define G3H 1536
#define G6H 3072

typedef __nv_bfloat16 bf16;

// ---------------- scratch (static device arrays) ---------------------------
__device__ float g_h32[2][BB * 512 * HH];
__device__ bf16  g_hhi[2][BB * 512 * HH];
__device__ bf16  g_hlo[2][BB * 512 * HH];
__device__ bf16  g_hidhi[(size_t)BB * 512 * 2 * HH];
__device__ bf16  g_hidlo[(size_t)BB * 512 * 2 * HH];
__device__ bf16  g_wthi[BB * 256 * HH];
__device__ bf16  g_wtlo[BB * 256 * HH];
__device__ bf16  g_ahi[BB * 256 * SS];
__device__ bf16  g_alo[BB * 256 * SS];
__device__ float g_gi[(size_t)BB * 256 * G6H];
__device__ float g_gh[(size_t)BB * 256 * G6H];
__device__ float g_annp[BB * G6H];
__device__ bf16  g_annhi[BB * HH];
__device__ bf16  g_annlo[BB * HH];
__device__ bf16  g_enchi[BB * SS * HH];
__device__ bf16  g_enclo[BB * SS * HH];
__device__ bf16  g_ewhi[(size_t)BB * G6H * SS];
__device__ bf16  g_ewlo[(size_t)BB * G6H * SS];
__device__ bf16  g_wihx_hi[G6H * HH], g_wihx_lo[G6H * HH];
__device__ bf16  g_wiha_hi[G6H * HH], g_wiha_lo[G6H * HH];
__device__ bf16  g_whh_hi[G6H * HH],  g_whh_lo[G6H * HH];
__device__ bf16  g_w1_hi[2 * HH * HH], g_w1_lo[2 * HH * HH];
__device__ bf16  g_w2_hi[VV * 2 * HH], g_w2_lo[VV * 2 * HH];

// epilogue modes
#define MODE_BIAS   0
#define MODE_SIG    1
#define MODE_OUT    2
#define MODE_BIAS2D 3
#define MODE_RAW    4

__device__ __forceinline__ int preorder_index(int d, int pos) {
    int idx = d;
#pragma unroll
    for (int i = 1; i <= DEPTH_; i++) {
        if (i <= d) {
            int bit = (pos >> (d - i)) & 1;
            idx += bit * ((1 << (DEPTH_ - i + 1)) - 1);
        }
    }
    return idx;
}

__device__ __forceinline__ void mma_bf16(float c[4],
                                         unsigned a0, unsigned a1,
                                         unsigned a2, unsigned a3,
                                         unsigned b0, unsigned b1) {
    asm volatile(
        "mma.sync.aligned.m16n8k16.row.col.f32.bf16.bf16.f32 "
        "{%0,%1,%2,%3}, {%4,%5,%6,%7}, {%8,%9}, {%0,%1,%2,%3};"
        : "+f"(c[0]), "+f"(c[1]), "+f"(c[2]), "+f"(c[3])
        : "r"(a0), "r"(a1), "r"(a2), "r"(a3), "r"(b0), "r"(b1));
}

__device__ __forceinline__ void split_bf16(float x, bf16& hi, bf16& lo) {
    hi = __float2bfloat16_rn(x);
    lo = __float2bfloat16_rn(x - __bfloat162float(hi));
}

__device__ __forceinline__ void cp16(void* dst, const void* src) {
    unsigned d = (unsigned)__cvta_generic_to_shared(dst);
    asm volatile("cp.async.cg.shared.global [%0], [%1], 16;"
                 :: "r"(d), "l"(src));
}

// ---------------- split helpers --------------------------------------------
__global__ __launch_bounds__(256) void split_mat(
    const float* __restrict__ src, int rows, int cols, int ld, int coloff,
    bf16* __restrict__ dhi, bf16* __restrict__ dlo)
{
    int idx = blockIdx.x * blockDim.x + threadIdx.x;
    if (idx >= rows * cols) return;
    int r = idx / cols;
    int c = idx - r * cols;
    float v = src[(size_t)r * ld + coloff + c];
    bf16 hi, lo;
    split_bf16(v, hi, lo);
    dhi[idx] = hi;
    dlo[idx] = lo;
}

// enc (S,B,H) -> planes (B,S,H)
__global__ __launch_bounds__(256) void split_enc(
    const float* __restrict__ enc, bf16* __restrict__ dhi,
    bf16* __restrict__ dlo)
{
    int idx = blockIdx.x * blockDim.x + threadIdx.x;
    if (idx >= SS * BB * HH) return;
    int h = idx & (HH - 1);
    int rem = idx >> 9;
    int b = rem & (BB - 1);
    int s = rem >> 6;
    float v = enc[idx];
    bf16 hi, lo;
    split_bf16(v, hi, lo);
    size_t o = ((size_t)b * SS + s) * HH + h;
    dhi[o] = hi;
    dlo[o] = lo;
}

// E (BB*SS rows, G6H cols, fp32) -> ew planes (b, G6H, SS) bf16
__global__ __launch_bounds__(256) void transpose_split(
    const float* __restrict__ E, bf16* __restrict__ dhi,
    bf16* __restrict__ dlo)
{
    __shared__ float tile[64][65];
    int b = blockIdx.x;
    int jt = blockIdx.y;
    int tx = threadIdx.x & 63;
    int ty = threadIdx.x >> 6;
    for (int s = ty; s < 64; s += 4)
        tile[s][tx] = E[((size_t)b * SS + s) * G6H + jt * 64 + tx];
    __syncthreads();
    for (int jr = ty; jr < 64; jr += 4) {
        float v = tile[tx][jr];
        bf16 hi, lo;
        split_bf16(v, hi, lo);
        size_t o = ((size_t)b * G6H + jt * 64 + jr) * SS + tx;
        dhi[o] = hi;
        dlo[o] = lo;
    }
}

// ---------------- bf16x3 mma.sync GEMM, cp.async 3-stage --------------------
// C(MxN) = A(MxK) @ Bw(NxK)^T ; A/B pre-split bf16 hi/lo planes (ld = K).
// blockIdx.z batches independent GEMMs: A += z*z_aoff, B += z*z_boff,
// C += z*z_coff, bias += z*z_biasoff (all element offsets, applied pre-loop).
#define BM 128
#define BN 128
#define BKT 16
#define PITCH 24
#define NSTAGE 3
#define PLANE_ELE (BM * PITCH)
#define STAGE_ELE (4 * PLANE_ELE)
#define GEMM_SMEM (NSTAGE * STAGE_ELE * 2)

__global__ __launch_bounds__(256, 2) void mma_gemm(
    const bf16* __restrict__ Ahi, const bf16* __restrict__ Alo,
    const bf16* __restrict__ Bhi, const bf16* __restrict__ Blo,
    const float* __restrict__ bias, float* __restrict__ C,
    bf16* __restrict__ Chi, bf16* __restrict__ Clo,
    int M, int N, int K, int mode, int n_nodes, int depth,
    long long z_aoff, long long z_boff, long long z_coff,
    long long z_biasoff)
{
    extern __shared__ bf16 smem[];

    const int tid = threadIdx.x;
    const int lane = tid & 31;
    const int wid = tid >> 5;
    const int warp_m = (wid & 1) * 64;
    const int warp_n = (wid >> 1) * 32;
    const int g = lane >> 2;
    const int t = lane & 3;

    const int row0 = blockIdx.y * BM;
    const int col0 = blockIdx.x * BN;

    const size_t z = blockIdx.z;
    const bf16* Ahi_p = Ahi + z * z_aoff;
    const bf16* Alo_p = Alo + z * z_aoff;
    const bf16* Bhi_p = Bhi + z * z_boff;
    const bf16* Blo_p = Blo + z * z_boff;
    const float* bias_p = bias ? (bias + z * z_biasoff) : bias;
    const size_t cofs = z * z_coff;

    const int lrow = tid >> 1;
    const int lk = (tid & 1) * 8;

    int arow = row0 + lrow; if (arow >= M) arow = M - 1;
    const size_t aoff = (size_t)arow * K + lk;
    const size_t boff = (size_t)(col0 + lrow) * K + lk;

    const int srow = lrow * PITCH + lk;

    auto load_stage = [&](int kt, int s) {
        bf16* st = smem + s * STAGE_ELE;
        size_t ka = aoff + (size_t)kt * BKT;
        size_t kb = boff + (size_t)kt * BKT;
        cp16(st + srow,                 Ahi_p + ka);
        cp16(st + PLANE_ELE + srow,     Alo_p + ka);
        cp16(st + 2 * PLANE_ELE + srow, Bhi_p + kb);
        cp16(st + 3 * PLANE_ELE + srow, Blo_p + kb);
        asm volatile("cp.async.commit_group;" ::: "memory");
    };

    float acc[4][4][4];
#pragma unroll
    for (int mi = 0; mi < 4; mi++)
#pragma unroll
        for (int ni = 0; ni < 4; ni++)
#pragma unroll
            for (int i = 0; i < 4; i++) acc[mi][ni][i] = 0.f;

    const int nkt = K / BKT;

    load_stage(0, 0);
    load_stage(1, 1);

    const int a_r = lane & 15;
    const int a_c = (lane >> 4) * 8;
    const int b_r = lane & 7;
    const int b_c = ((lane >> 3) & 1) * 8;

    int s = 0;
    for (int kt = 0; kt < nkt; kt++) {
        asm volatile("cp.async.wait_group 1;" ::: "memory");
        __syncthreads();

        bf16* st = smem + s * STAGE_ELE;
        bf16* pAhi = st;
        bf16* pAlo = st + PLANE_ELE;
        bf16* pBhi = st + 2 * PLANE_ELE;
        bf16* pBlo = st + 3 * PLANE_ELE;

        unsigned ah[4][4], al[4][4], bh[4][2], bl[4][2];
#pragma unroll
        for (int mi = 0; mi < 4; mi++) {
            int r = warp_m + mi * 16 + a_r;
            unsigned ad = (unsigned)__cvta_generic_to_shared(
                pAhi + r * PITCH + a_c);
            asm volatile("ldmatrix.sync.aligned.m8n8.x4.shared.b16 "
                         "{%0,%1,%2,%3}, [%4];"
                         : "=r"(ah[mi][0]), "=r"(ah[mi][1]),
                           "=r"(ah[mi][2]), "=r"(ah[mi][3]) : "r"(ad));
            unsigned ad2 = (unsigned)__cvta_generic_to_shared(
                pAlo + r * PITCH + a_c);
            asm volatile("ldmatrix.sync.aligned.m8n8.x4.shared.b16 "
                         "{%0,%1,%2,%3}, [%4];"
                         : "=r"(al[mi][0]), "=r"(al[mi][1]),
                           "=r"(al[mi][2]), "=r"(al[mi][3]) : "r"(ad2));
        }
#pragma unroll
        for (int ni = 0; ni < 4; ni++) {
            int r = warp_n + ni * 8 + b_r;
            unsigned bd = (unsigned)__cvta_generic_to_shared(
                pBhi + r * PITCH + b_c);
            asm volatile("ldmatrix.sync.aligned.m8n8.x2.shared.b16 "
                         "{%0,%1}, [%2];"
                         : "=r"(bh[ni][0]), "=r"(bh[ni][1]) : "r"(bd));
            unsigned bd2 = (unsigned)__cvta_generic_to_shared(
                pBlo + r * PITCH + b_c);
            asm volatile("ldmatrix.sync.aligned.m8n8.x2.shared.b16 "
                         "{%0,%1}, [%2];"
                         : "=r"(bl[ni][0]), "=r"(bl[ni][1]) : "r"(bd2));
        }

#pragma unroll
        for (int mi = 0; mi < 4; mi++)
#pragma unroll
            for (int ni = 0; ni < 4; ni++)
                mma_bf16(acc[mi][ni], ah[mi][0], ah[mi][1], ah[mi][2],
                         ah[mi][3], bh[ni][0], bh[ni][1]);
#pragma unroll
        for (int mi = 0; mi < 4; mi++)
#pragma unroll
            for (int ni = 0; ni < 4; ni++)
                mma_bf16(acc[mi][ni], al[mi][0], al[mi][1], al[mi][2],
                         al[mi][3], bh[ni][0], bh[ni][1]);
#pragma unroll
        for (int mi = 0; mi < 4; mi++)
#pragma unroll
            for (int ni = 0; ni < 4; ni++)
                mma_bf16(acc[mi][ni], ah[mi][0], ah[mi][1], ah[mi][2],
                         ah[mi][3], bl[ni][0], bl[ni][1]);

        if (kt + 2 < nkt) {
            int ns = s + 2; if (ns >= NSTAGE) ns -= NSTAGE;
            load_stage(kt + 2, ns);
        } else {
            asm volatile("cp.async.commit_group;" ::: "memory");
        }
        s++; if (s == NSTAGE) s = 0;
    }

    // epilogue
#pragma unroll
    for (int mi = 0; mi < 4; mi++) {
#pragma unroll
        for (int i = 0; i < 4; i++) {
            int r = row0 + warp_m + mi * 16 + g + (i >> 1) * 8;
            if (r >= M) continue;
#pragma unroll
            for (int ni = 0; ni < 4; ni++) {
                int c = col0 + warp_n + ni * 8 + t * 2 + (i & 1);
                float v = acc[mi][ni][i];
                if (mode == MODE_BIAS) {
                    C[cofs + (size_t)r * N + c] = v + bias_p[c];
                } else if (mode == MODE_SIG) {
                    float sgm = 1.f / (1.f + expf(-(v + bias_p[c])));
                    bf16 hi, lo;
                    split_bf16(sgm, hi, lo);
                    Chi[(size_t)r * N + c] = hi;
                    Clo[(size_t)r * N + c] = lo;
                } else if (mode == MODE_OUT) {
                    int b = r / n_nodes;
                    int node = r - b * n_nodes;
                    int p = preorder_index(depth, node);
                    C[((size_t)p * BB + b) * VV + c] = v + bias_p[c];
                } else if (mode == MODE_BIAS2D) {
                    int b = r / n_nodes;
                    C[(size_t)r * N + c] = v + bias_p[(size_t)b * N + c];
                } else { // MODE_RAW
                    C[cofs + (size_t)r * N + c] = v;
                }
            }
        }
    }
}

// ---------------- fused attention ------------------------------------------
// write_a=1: emit softmax probs as bf16 planes (M x 64); skip weighted sum.
__global__ __launch_bounds__(128) void attn_kernel(
    const float* __restrict__ h, const float* __restrict__ enc,
    bf16* __restrict__ wthi, bf16* __restrict__ wtlo,
    bf16* __restrict__ ahi, bf16* __restrict__ alo,
    int n, int write_a)
{
    int m = blockIdx.x;
    int b = m / n;
    int t = threadIdx.x;

    __shared__ float sh[HH];
    __shared__ float part[128];
    __shared__ float sc[SS];

    const float* hrow = h + (size_t)m * HH;
    for (int i = t; i < HH; i += 128) sh[i] = hrow[i];
    __syncthreads();

    int s = t & 63;
    int half = t >> 6;
    const float* er = enc + ((size_t)s * BB + b) * HH + half * 256;
    float acc = 0.f;
#pragma unroll 8
    for (int k = 0; k < 256; k++) acc = fmaf(sh[half * 256 + k], er[k], acc);
    part[t] = acc;
    __syncthreads();

    if (t < SS) sc[t] = part[t] + part[t + 64];
    __syncthreads();

    float mx = -1e30f;
#pragma unroll
    for (int i = 0; i < SS; i++) mx = fmaxf(mx, sc[i]);
    __syncthreads();
    if (t < SS) sc[t] = expf(sc[t] - mx);
    __syncthreads();
    float sum = 0.f;
#pragma unroll
    for (int i = 0; i < SS; i++) sum += sc[i];
    float inv = 1.f / sum;

    if (write_a) {
        if (t < SS) {
            float av = sc[t] * inv;
            bf16 hh_, ll_;
            split_bf16(av, hh_, ll_);
            ahi[(size_t)m * SS + t] = hh_;
            alo[(size_t)m * SS + t] = ll_;
        }
        return;
    }

    for (int hi_ = t; hi_ < HH; hi_ += 128) {
        float acc2 = 0.f;
#pragma unroll 8
        for (int s2 = 0; s2 < SS; s2++)
            acc2 = fmaf(sc[s2], enc[((size_t)s2 * BB + b) * HH + hi_], acc2);
        float v = acc2 * inv;
        bf16 h_, l_;
        split_bf16(v, h_, l_);
        wthi[(size_t)m * HH + hi_] = h_;
        wtlo[(size_t)m * HH + hi_] = l_;
    }
}

// ---------------- GRU gate combine (both children fused) -------------------
__global__ __launch_bounds__(256) void gru_combine(
    const float* __restrict__ gi, const float* __restrict__ gh,
    const float* __restrict__ h, float* __restrict__ h32n,
    bf16* __restrict__ hhin, bf16* __restrict__ hlon,
    int n, int total)
{
    int idx = blockIdx.x * blockDim.x + threadIdx.x;
    if (idx >= total) return;
    int k = idx & (HH - 1);
    int child = (idx >> 9) & 1;
    int m = idx >> 10;
    int b = m / n;
    int node = m - b * n;

    size_t gb = (size_t)m * G6H + (size_t)child * G3H;
    float ir = gi[gb + k], iz = gi[gb + HH + k], in_ = gi[gb + 2 * HH + k];
    float hr = gh[gb + k], hz = gh[gb + HH + k], hn = gh[gb + 2 * HH + k];

    float r = 1.f / (1.f + expf(-(ir + hr)));
    float z = 1.f / (1.f + expf(-(iz + hz)));
    float nn = tanhf(in_ + r * hn);
    float hv = h[(size_t)m * HH + k];
    float out = (1.f - z) * nn + z * hv;

    size_t oidx = ((size_t)b * (2 * n) + 2 * node + child) * HH + k;
    h32n[oidx] = out;
    bf16 oh, ol;
    split_bf16(out, oh, ol);
    hhin[oidx] = oh;
    hlon[oidx] = ol;
}

// ---------------- orchestration --------------------------------------------
static void launch_gemm(const bf16* Ah, const bf16* Al,
                        const bf16* Bh, const bf16* Bl,
                        const float* bias, float* C, bf16* Ch, bf16* Cl,
                        int M, int N, int K, int mode, int nn, int dd)
{
    dim3 grid(N / BN, (M + BM - 1) / BM);
    mma_gemm<<<grid, 256, GEMM_SMEM>>>(Ah, Al, Bh, Bl, bias, C, Ch, Cl,
                                       M, N, K, mode, nn, dd, 0, 0, 0, 0);
}

extern "C" void kernel_launch(void* const* d_in, const int* in_sizes, int n_in,
                              void* d_out, int out_size)
{
    (void)in_sizes; (void)n_in; (void)out_size;
    const float* root  = (const float*)d_in[0];
    const float* ann   = (const float*)d_in[1];
    const float* enc   = (const float*)d_in[2];
    // d_in[3] = source_mask: constant all-True, unused
    const float* w_ih  = (const float*)d_in[4];
    const float* w_hh  = (const float*)d_in[5];
    const float* b_ih  = (const float*)d_in[6];
    const float* b_hh  = (const float*)d_in[7];
    const float* W1    = (const float*)d_in[8];
    const float* b1    = (const float*)d_in[9];
    const float* W2    = (const float*)d_in[10];
    const float* b2    = (const float*)d_in[11];
    float* out = (float*)d_out;

    cudaFuncSetAttribute(mma_gemm,
                         cudaFuncAttributeMaxDynamicSharedMemorySize,
                         GEMM_SMEM);

    float *h32, *gi, *gh, *annp;
    bf16 *hhi, *hlo, *hidhi, *hidlo, *wthi, *wtlo, *ahi, *alo;
    bf16 *annhi, *annlo, *enchi, *enclo, *ewhi, *ewlo;
    bf16 *wihxh, *wihxl, *wihah, *wihal, *whhh, *whhl, *w1h, *w1l, *w2h, *w2l;
    cudaGetSymbolAddress((void**)&h32,   g_h32);
    cudaGetSymbolAddress((void**)&hhi,   g_hhi);
    cudaGetSymbolAddress((void**)&hlo,   g_hlo);
    cudaGetSymbolAddress((void**)&hidhi, g_hidhi);
    cudaGetSymbolAddress((void**)&hidlo, g_hidlo);
    cudaGetSymbolAddress((void**)&wthi,  g_wthi);
    cudaGetSymbolAddress((void**)&wtlo,  g_wtlo);
    cudaGetSymbolAddress((void**)&ahi,   g_ahi);
    cudaGetSymbolAddress((void**)&alo,   g_alo);
    cudaGetSymbolAddress((void**)&gi,    g_gi);
    cudaGetSymbolAddress((void**)&gh,    g_gh);
    cudaGetSymbolAddress((void**)&annp,  g_annp);
    cudaGetSymbolAddress((void**)&annhi, g_annhi);
    cudaGetSymbolAddress((void**)&annlo, g_annlo);
    cudaGetSymbolAddress((void**)&enchi, g_enchi);
    cudaGetSymbolAddress((void**)&enclo, g_enclo);
    cudaGetSymbolAddress((void**)&ewhi,  g_ewhi);
    cudaGetSymbolAddress((void**)&ewlo,  g_ewlo);
    cudaGetSymbolAddress((void**)&wihxh, g_wihx_hi);
    cudaGetSymbolAddress((void**)&wihxl, g_wihx_lo);
    cudaGetSymbolAddress((void**)&wihah, g_wiha_hi);
    cudaGetSymbolAddress((void**)&wihal, g_wiha_lo);
    cudaGetSymbolAddress((void**)&whhh,  g_whh_hi);
    cudaGetSymbolAddress((void**)&whhl,  g_whh_lo);
    cudaGetSymbolAddress((void**)&w1h,   g_w1_hi);
    cudaGetSymbolAddress((void**)&w1l,   g_w1_lo);
    cudaGetSymbolAddress((void**)&w2h,   g_w2_hi);
    cudaGetSymbolAddress((void**)&w2l,   g_w2_lo);

    const size_t HSLOT = (size_t)BB * 512 * HH;
    float* h32buf[2] = {h32, h32 + HSLOT};
    bf16*  hhibuf[2] = {hhi, hhi + HSLOT};
    bf16*  hlobuf[2] = {hlo, hlo + HSLOT};

    // kernel launch order: #5 is the big E-GEMM (ncu empirically captures
    // the 5th kernel launch; memcpies don't count)
    split_enc<<<(SS * BB * HH + 255) / 256, 256>>>(enc, enchi, enclo);   // 1
    split_mat<<<(G6H * HH + 255) / 256, 256>>>(w_ih, G6H, HH, 2 * HH, HH,
                                               wihxh, wihxl);            // 2
    split_mat<<<(BB * HH + 255) / 256, 256>>>(ann, BB, HH, HH, 0,
                                              annhi, annlo);             // 3
    split_mat<<<(G6H * HH + 255) / 256, 256>>>(w_ih, G6H, HH, 2 * HH, 0,
                                               wihah, wihal);            // 4

    // 5: E = enc_flat(4096 x 512) @ Wx^T -> fp32 staged in g_gh  [ncu target]
    launch_gemm(enchi, enclo, wihxh, wihxl, nullptr, gh, nullptr, nullptr,
                BB * SS, G6H, HH, MODE_RAW, 0, 0);

    // 6: annp = ann @ w_ih[:, :, :H]^T + b_ih   (64 x 3072)
    launch_gemm(annhi, annlo, wihah, wihal, b_ih, annp, nullptr, nullptr,
                BB, G6H, HH, MODE_BIAS, 0, 0);

    transpose_split<<<dim3(BB, G6H / 64), 256>>>(gh, ewhi, ewlo);

    cudaMemcpyAsync(h32buf[0], root, (size_t)BB * HH * sizeof(float),
                    cudaMemcpyDeviceToDevice);
    split_mat<<<(BB * HH + 255) / 256, 256>>>(root, BB, HH, HH, 0,
                                              hhibuf[0], hlobuf[0]);
    split_mat<<<(G6H * HH + 255) / 256, 256>>>(w_hh, G6H, HH, HH, 0,
                                               whhh, whhl);
    split_mat<<<(2 * HH * HH + 255) / 256, 256>>>(W1, 2 * HH, HH, HH, 0,
                                                  w1h, w1l);
    split_mat<<<(VV * 2 * HH + 255) / 256, 256>>>(W2, VV, 2 * HH, 2 * HH, 0,
                                                  w2h, w2l);

    int cur = 0;
    for (int d = 0; d <= DEPTH_; d++) {
        int n = 1 << d;
        int M = BB * n;

        // hid = sigmoid(h @ W1^T + b1) -> split planes   (M x 1024)
        launch_gemm(hhibuf[cur], hlobuf[cur], w1h, w1l, b1, nullptr,
                    hidhi, hidlo, M, 2 * HH, HH, MODE_SIG, 0, 0);

        // prods -> scattered into out (preorder)   (M x 512)
        launch_gemm(hidhi, hidlo, w2h, w2l, b2, out, nullptr, nullptr,
                    M, VV, 2 * HH, MODE_OUT, n, d);

        if (d < DEPTH_) {
            int use_a = (n >= 32) ? 1 : 0;
            attn_kernel<<<M, 128>>>(h32buf[cur], enc, wthi, wtlo,
                                    ahi, alo, n, use_a);

            if (use_a) {
                // per-batch: gi[z] = a[z] @ ew[z]^T + annp[z]  (n x 3072, K=64)
                dim3 grid(G6H / BN, (n + BM - 1) / BM, BB);
                mma_gemm<<<grid, 256, GEMM_SMEM>>>(
                    ahi, alo, ewhi, ewlo, annp, gi, nullptr, nullptr,
                    n, G6H, SS, MODE_BIAS, 0, 0,
                    (long long)n * SS,          // z_aoff
                    (long long)G6H * SS,        // z_boff
                    (long long)n * G6H,         // z_coff
                    (long long)G6H);            // z_biasoff
            } else {
                // gi = wt @ w_ih[:, :, H:]^T + annp   (M x 3072, K = 512)
                launch_gemm(wthi, wtlo, wihxh, wihxl, annp, gi,
                            nullptr, nullptr, M, G6H, HH, MODE_BIAS2D, n, 0);
            }

            // gh = h @ w_hh^T + b_hh              (M x 3072)
            launch_gemm(hhibuf[cur], hlobuf[cur], whhh, whhl, b_hh, gh,
                        nullptr, nullptr, M, G6H, HH, MODE_BIAS, 0, 0);

            int total = M * 2 * HH;
            gru_combine<<<(total + 255) / 256, 256>>>(
                gi, gh, h32buf[cur], h32buf[cur ^ 1],
                hhibuf[cur ^ 1], hlobuf[cur ^ 1], n, total);

            cur ^= 1;
        }
    }
}